// round 15
// baseline (speedup 1.0000x reference)
#include <cuda_runtime.h>
#include <cuda_fp16.h>
#include <cstdint>

#define BB 2
#define CC 256
#define HH 48
#define WW 48
#define HWP 2304
#define DM 256
#define NH 8
#define DK 32
#define QK_SCALE 0.17677669529663689f   // 1/sqrt(32)
#define LOG2E 1.4426950408889634f
#define QSC (QK_SCALE * LOG2E)           // folded into Q at projection time
#define EXP_OFF 7.0f                     // folded into bias table; cancels in softmax
#define QPAD 40                          // f16 pitch = 80B (16B multiple)
#define WPAD 40
#define NSPLIT 3
#define NTILE (HWP / 64)                 // 36
#define TPS (NTILE / NSPLIT)             // 12 tiles per split

// ---------------- scratch (allocation-free) ----------------
__device__ __half g_Qh[BB * HWP * DM];
__device__ __half g_Kh[BB * HWP * DM];
__device__ __half g_Vh[BB * HWP * DM];
__device__ __half g_Oph[NSPLIT * BB * HWP * DM];   // partial attention out
__device__ float  g_rsP[NSPLIT * BB * NH * HWP];   // partial row sums
__device__ __half g_xh[BB * HWP * CC];             // x transposed (b,p,c)
__device__ __half g_Wqh[DM * CC];
__device__ __half g_Wkh[DM * CC];
__device__ __half g_Wvh[DM * CC];
__device__ __half g_Woh[CC * DM];
__device__ __half g_dtabH[95 * 95];                // f16: lam*exp(-d)*log2e - 7
__device__ __half g_biasH[HWP * HWP];              // fragment-ordered bias (f16)

// ---------------- helpers ----------------
__device__ __forceinline__ uint32_t smem_u32(const void* p) {
    uint32_t a;
    asm("{ .reg .u64 t; cvta.to.shared.u64 t, %1; cvt.u32.u64 %0, t; }" : "=r"(a) : "l"(p));
    return a;
}
__device__ __forceinline__ void ldmx4(uint32_t& r0, uint32_t& r1, uint32_t& r2, uint32_t& r3, uint32_t a) {
    asm volatile("ldmatrix.sync.aligned.m8n8.x4.shared.b16 {%0,%1,%2,%3}, [%4];"
                 : "=r"(r0), "=r"(r1), "=r"(r2), "=r"(r3) : "r"(a));
}
__device__ __forceinline__ void ldmx4t(uint32_t& r0, uint32_t& r1, uint32_t& r2, uint32_t& r3, uint32_t a) {
    asm volatile("ldmatrix.sync.aligned.m8n8.x4.trans.shared.b16 {%0,%1,%2,%3}, [%4];"
                 : "=r"(r0), "=r"(r1), "=r"(r2), "=r"(r3) : "r"(a));
}
__device__ __forceinline__ void mma16816f(float* c, const uint32_t* a, const uint32_t* b) {
    asm volatile("mma.sync.aligned.m16n8k16.row.col.f32.f16.f16.f32 "
                 "{%0,%1,%2,%3},{%4,%5,%6,%7},{%8,%9},{%0,%1,%2,%3};"
                 : "+f"(c[0]), "+f"(c[1]), "+f"(c[2]), "+f"(c[3])
                 : "r"(a[0]), "r"(a[1]), "r"(a[2]), "r"(a[3]), "r"(b[0]), "r"(b[1]));
}
__device__ __forceinline__ void mma16816h(uint32_t* d, const uint32_t* a, uint32_t b0, uint32_t b1) {
    asm volatile("mma.sync.aligned.m16n8k16.row.col.f16.f16.f16.f16 "
                 "{%0,%1},{%2,%3,%4,%5},{%6,%7},{%0,%1};"
                 : "+r"(d[0]), "+r"(d[1])
                 : "r"(a[0]), "r"(a[1]), "r"(a[2]), "r"(a[3]), "r"(b0), "r"(b1));
}
__device__ __forceinline__ uint32_t f2h2(float lo, float hi) {
    __half2 h = __floats2half2_rn(lo, hi);
    return *(uint32_t*)&h;
}
__device__ __forceinline__ uint32_t hadd2u(uint32_t a, uint32_t b) {
    uint32_t d;
    asm("add.rn.f16x2 %0, %1, %2;" : "=r"(d) : "r"(a), "r"(b));
    return d;
}
__device__ __forceinline__ uint32_t hmul2u(uint32_t a, uint32_t b) {
    uint32_t d;
    asm("mul.rn.f16x2 %0, %1, %2;" : "=r"(d) : "r"(a), "r"(b));
    return d;
}
__device__ __forceinline__ uint32_t hex2u(uint32_t a) {
    uint32_t d;
    asm("ex2.approx.f16x2 %0, %1;" : "=r"(d) : "r"(a));
    return d;
}
__device__ __forceinline__ float2 h2f2(uint32_t u) {
    __half2 h = *(__half2*)&u;
    return __half22float2(h);
}
#define CPA16(dst, src) asm volatile("cp.async.cg.shared.global [%0], [%1], 16;" :: "r"(dst), "l"(src))
#define CPA_COMMIT()    asm volatile("cp.async.commit_group;")
#define CPA_WAIT0()     asm volatile("cp.async.wait_group 0;")

// ---------------------------------------------------------------------------
// Prep A (merged): blocks [0,512): W fp32->f16; blocks [512,548): dtab (f16,
// with -EXP_OFF folded).
// ---------------------------------------------------------------------------
__global__ __launch_bounds__(256) void prep_kernel(
    const float* __restrict__ lam_p,
    const float* __restrict__ Wq, const float* __restrict__ Wk,
    const float* __restrict__ Wv, const float* __restrict__ Wo)
{
    const int bx = blockIdx.x;
    if (bx < 512) {
        const int idx = bx * 256 + threadIdx.x;
        const int mat = idx >> 15;
        const int off = idx & 32767;
        const float* s = (mat == 0) ? Wq : ((mat == 1) ? Wk : ((mat == 2) ? Wv : Wo));
        uint32_t* d = (uint32_t*)((mat == 0) ? g_Wqh : ((mat == 1) ? g_Wkh : ((mat == 2) ? g_Wvh : g_Woh)));
        d[off] = f2h2(s[off * 2], s[off * 2 + 1]);
    } else {
        const int idx = (bx - 512) * 256 + threadIdx.x;
        if (idx >= 95 * 95) return;
        const float lam2 = (*lam_p) * LOG2E;
        const int dy = idx / 95 - 47;
        const int dx = idx % 95 - 47;
        const float t = lam2 * __expf(-sqrtf((float)(dy * dy + dx * dx))) - EXP_OFF;
        g_dtabH[idx] = __float2half(t);
    }
}

// ---------------------------------------------------------------------------
// Prep B: expand bias matrix in MMA-fragment order.
// ---------------------------------------------------------------------------
__global__ __launch_bounds__(256) void bias_fill_kernel()
{
    const int idx = blockIdx.x * 256 + threadIdx.x;   // HWP*HWP/2 u32s
    const int blk  = idx >> 11;
    const int rem  = idx & 2047;
    const int w    = rem >> 9;
    const int rem2 = rem & 511;
    const int mn   = rem2 >> 6;
    const int rr   = (rem2 >> 5) & 1;
    const int lane = rem2 & 31;
    const int m = mn >> 3, n = mn & 7;
    const int R = blk / 36, T = blk - R * 36;
    const int i = R * 128 + w * 32 + m * 16 + (lane >> 2) + rr * 8;
    const int j = T * 64 + n * 8 + 2 * (lane & 3);
    const int yi = i / WW, xi = i - yi * WW;
    const int yj0 = j / WW,      xj0 = j - yj0 * WW;
    const int yj1 = (j + 1) / WW, xj1 = (j + 1) - yj1 * WW;
    const unsigned short h0 = *(const unsigned short*)&g_dtabH[(yi - yj0 + 47) * 95 + (xi - xj0 + 47)];
    const unsigned short h1 = *(const unsigned short*)&g_dtabH[(yi - yj1 + 47) * 95 + (xi - xj1 + 47)];
    ((uint32_t*)g_biasH)[idx] = (uint32_t)h0 | ((uint32_t)h1 << 16);
}

// ---------------------------------------------------------------------------
// Prep C: transpose+convert x (b,c,p) fp32 -> g_xh (b,p,c) f16 (vectorized).
// ---------------------------------------------------------------------------
__global__ __launch_bounds__(256) void xt_kernel(const float* __restrict__ x)
{
    __shared__ float ts[64][65];
    const int b  = blockIdx.z;
    const int pB = blockIdx.x * 64;
    const int cB = blockIdx.y * 64;
    #pragma unroll
    for (int i = threadIdx.x; i < 1024; i += 256) {
        const int c  = i >> 4;
        const int pq = (i & 15) * 4;
        const float4 v = *(const float4*)&x[((size_t)b * CC + cB + c) * HWP + pB + pq];
        ts[c][pq + 0] = v.x;
        ts[c][pq + 1] = v.y;
        ts[c][pq + 2] = v.z;
        ts[c][pq + 3] = v.w;
    }
    __syncthreads();
    #pragma unroll
    for (int i = threadIdx.x; i < 1024; i += 256) {
        const int p  = i >> 4;
        const int cq = (i & 15) * 4;
        uint2 o;
        o.x = f2h2(ts[cq + 0][p], ts[cq + 1][p]);
        o.y = f2h2(ts[cq + 2][p], ts[cq + 3][p]);
        *(uint2*)(g_xh + ((size_t)(b * HWP + pB + p) * CC + cB + cq)) = o;
    }
}

// ---------------------------------------------------------------------------
// Kernel 1: HMMA fused QKV + pe + bias; Q pre-scaled by QSC (unchanged).
// ---------------------------------------------------------------------------
__global__ __launch_bounds__(256) void qkv_mma_kernel(
    const float* __restrict__ bq, const float* __restrict__ bk, const float* __restrict__ bv)
{
    __shared__ __align__(16) __half As[2][64 * QPAD];
    __shared__ __align__(16) __half Ws[2][3][64 * WPAD];

    const int tid  = threadIdx.x;
    const int warp = tid >> 5;
    const int lane = tid & 31;

    const int gp    = blockIdx.x * 64;
    const int b     = gp / HWP;
    const int pb    = gp - b * HWP;
    const int dBase = blockIdx.y * 64;
    const bool use_y = (dBase >= 128);

    const uint32_t asA = smem_u32(As);
    const uint32_t wsA = smem_u32(Ws);

    const __half* gW[3] = { g_Wqh, g_Wkh, g_Wvh };

    auto load_chunk = [&](int s, int c0) {
        const char* ab = (const char*)g_xh + ((size_t)(b * HWP + pb) * CC + c0) * 2;
        {
            const int i = tid;
            const int r = i >> 2, q = i & 3;
            CPA16(asA + s * 5120 + r * 80 + q * 16, ab + (size_t)r * (CC * 2) + q * 16);
        }
        #pragma unroll
        for (int i = tid; i < 768; i += 256) {
            const int mat = i / 256;
            const int rem = i - mat * 256;
            const int r = rem >> 2, q = rem & 3;
            const char* wb = (const char*)gW[mat] + ((size_t)(dBase + r) * CC + c0) * 2;
            CPA16(wsA + s * 15360 + mat * 5120 + r * 80 + q * 16, wb + q * 16);
        }
        CPA_COMMIT();
    };

    const int mw = warp >> 2;
    const int nw = warp & 3;

    float acc[3][2][2][4] = {};

    load_chunk(0, 0);

    for (int c = 0; c < 8; c++) {
        CPA_WAIT0();
        __syncthreads();
        if (c < 7) load_chunk((c + 1) & 1, (c + 1) * 32);

        const int s = c & 1;
        const __half* Ab = As[s];

        const int arow = (lane & 7) + ((lane >> 3) & 1) * 8;
        const int acol = (lane >> 4) * 8;
        const int brow = (lane & 7) + ((lane >> 4) & 1) * 8;
        const int bcol = ((lane >> 3) & 1) * 8;

        #pragma unroll
        for (int ks = 0; ks < 2; ks++) {
            uint32_t af[2][4];
            #pragma unroll
            for (int mt = 0; mt < 2; mt++) {
                uint32_t a = smem_u32(Ab + (mw * 32 + mt * 16 + arow) * QPAD + ks * 16 + acol);
                ldmx4(af[mt][0], af[mt][1], af[mt][2], af[mt][3], a);
            }
            #pragma unroll
            for (int mat = 0; mat < 3; mat++) {
                uint32_t bf[4];
                uint32_t a = smem_u32(&Ws[s][mat][(nw * 16 + brow) * WPAD + ks * 16 + bcol]);
                ldmx4(bf[0], bf[1], bf[2], bf[3], a);
                #pragma unroll
                for (int mt = 0; mt < 2; mt++) {
                    mma16816f(acc[mat][mt][0], af[mt], bf);
                    mma16816f(acc[mat][mt][1], af[mt], bf + 2);
                }
            }
        }
    }

    __syncthreads();
    __half* pes = (__half*)As;
    for (int i = tid; i < 48 * 64; i += 256) {
        const int coord = i >> 6;
        const int dloc  = i & 63;
        const int dl    = (dBase + dloc) - (use_y ? 128 : 0);
        const float freq = __expf(-(float)(dl >> 1) * 0.14391156642875743f);
        const float arg  = (float)coord * freq;
        pes[i] = __float2half((dl & 1) ? __cosf(arg) : __sinf(arg));
    }
    __syncthreads();

    const int c2 = 2 * (lane & 3);
    #pragma unroll
    for (int mt = 0; mt < 2; mt++) {
        #pragma unroll
        for (int rr = 0; rr < 2; rr++) {
            const int ploc = mw * 32 + mt * 16 + (lane >> 2) + rr * 8;
            const int p    = pb + ploc;
            const int coord = use_y ? (p / WW) : (p % WW);
            const size_t rowIdx = ((size_t)b * HWP + p) * DM + dBase;
            #pragma unroll
            for (int nt = 0; nt < 2; nt++) {
                const int dloc = nw * 16 + nt * 8 + c2;
                const int d    = dBase + dloc;
                const float pe0 = __half2float(pes[coord * 64 + dloc]);
                const float pe1 = __half2float(pes[coord * 64 + dloc + 1]);
                const float q0 = (acc[0][mt][nt][rr * 2 + 0] + bq[d]     + pe0) * QSC;
                const float q1 = (acc[0][mt][nt][rr * 2 + 1] + bq[d + 1] + pe1) * QSC;
                const float k0 = acc[1][mt][nt][rr * 2 + 0] + bk[d]     + pe0;
                const float k1 = acc[1][mt][nt][rr * 2 + 1] + bk[d + 1] + pe1;
                const float v0 = acc[2][mt][nt][rr * 2 + 0] + bv[d];
                const float v1 = acc[2][mt][nt][rr * 2 + 1] + bv[d + 1];
                *(uint32_t*)(g_Qh + rowIdx + dloc) = f2h2(q0, q1);
                *(uint32_t*)(g_Kh + rowIdx + dloc) = f2h2(k0, k1);
                *(uint32_t*)(g_Vh + rowIdx + dloc) = f2h2(v0, v1);
            }
        }
    }
}

// ---------------------------------------------------------------------------
// Kernel 2: f16 HMMA flash attention, KV-split x3, bias as MMA C-init.
// CTA 128 thr, 5 CTAs/SM allowed. Grid (18, 16, NSPLIT).
// ---------------------------------------------------------------------------
__global__ __launch_bounds__(128, 5) void attn_mma_kernel()
{
    __shared__ __align__(16) __half Qs[128 * QPAD];
    __shared__ __align__(16) __half Ks[2][64 * QPAD];
    __shared__ __align__(16) __half Vs[2][64 * QPAD];

    const int tid  = threadIdx.x;
    const int warp = tid >> 5;
    const int lane = tid & 31;
    const int b    = blockIdx.y >> 3;
    const int h    = blockIdx.y & 7;
    const int rowBase = blockIdx.x * 128;
    const int z    = blockIdx.z;
    const int tBeg = z * TPS;

    const uint32_t ksA = smem_u32(Ks);
    const uint32_t vsA = smem_u32(Vs);

    auto issue_tile = [&](int t, int s) {
        const int jt = t * 64;
        const char* kb = (const char*)g_Kh + ((size_t)(b * HWP + jt) * DM + h * DK) * 2;
        const char* vb = (const char*)g_Vh + ((size_t)(b * HWP + jt) * DM + h * DK) * 2;
        #pragma unroll
        for (int i = tid; i < 256; i += 128) {
            const int r = i >> 2, q = i & 3;
            CPA16(ksA + s * 5120 + r * 80 + q * 16, kb + (size_t)r * (DM * 2) + q * 16);
            CPA16(vsA + s * 5120 + r * 80 + q * 16, vb + (size_t)r * (DM * 2) + q * 16);
        }
        CPA_COMMIT();
    };

    {
        const __half* qsrc = g_Qh + (size_t)(b * HWP + rowBase) * DM + h * DK;
        #pragma unroll
        for (int i = tid; i < 512; i += 128) {
            const int r = i >> 2, q = i & 3;
            *(uint4*)(Qs + r * QPAD + q * 8) = *(const uint4*)(qsrc + (size_t)r * DM + q * 8);
        }
    }
    issue_tile(tBeg, 0);
    __syncthreads();

    uint32_t qa[2][2][4];
    {
        const int arow = (lane & 7) + ((lane >> 3) & 1) * 8;
        const int acol = (lane >> 4) * 8;
        #pragma unroll
        for (int m = 0; m < 2; m++)
            #pragma unroll
            for (int ks = 0; ks < 2; ks++) {
                uint32_t a = smem_u32(Qs + (warp * 32 + m * 16 + arow) * QPAD + ks * 16 + acol);
                ldmx4(qa[m][ks][0], qa[m][ks][1], qa[m][ks][2], qa[m][ks][3], a);
            }
    }

    const int c2 = 2 * (lane & 3);
    const uint32_t* bbase = (const uint32_t*)g_biasH
        + (size_t)blockIdx.x * 36 * 2048 + warp * 512 + lane;

    uint32_t o[2][4][2];
    uint32_t rsum2[2][2];
    #pragma unroll
    for (int m = 0; m < 2; m++) {
        #pragma unroll
        for (int n = 0; n < 4; n++) { o[m][n][0] = 0u; o[m][n][1] = 0u; }
        rsum2[m][0] = 0u; rsum2[m][1] = 0u;
    }

    for (int t = 0; t < TPS; t++) {
        uint32_t S[2][8][2];
        {
            const uint32_t* bt = bbase + (size_t)(tBeg + t) * 2048;
            #pragma unroll
            for (int m = 0; m < 2; m++)
                #pragma unroll
                for (int n = 0; n < 8; n++) {
                    S[m][n][0] = __ldg(bt + (m * 8 + n) * 64);
                    S[m][n][1] = __ldg(bt + (m * 8 + n) * 64 + 32);
                }
        }

        CPA_WAIT0();
        __syncthreads();
        if (t < TPS - 1) issue_tile(tBeg + t + 1, (t + 1) & 1);
        const int s = t & 1;

        {
            const int brow = (lane & 7) + ((lane >> 4) & 1) * 8;
            const int bcol = ((lane >> 3) & 1) * 8;
            #pragma unroll
            for (int np = 0; np < 4; np++) {
                #pragma unroll
                for (int ks = 0; ks < 2; ks++) {
                    uint32_t kf[4];
                    uint32_t a = smem_u32(&Ks[s][(np * 16 + brow) * QPAD + ks * 16 + bcol]);
                    ldmx4(kf[0], kf[1], kf[2], kf[3], a);
                    #pragma unroll
                    for (int m = 0; m < 2; m++) {
                        mma16816h(S[m][2 * np],     qa[m][ks], kf[0], kf[1]);
                        mma16816h(S[m][2 * np + 1], qa[m][ks], kf[2], kf[3]);
                    }
                }
            }
        }

        #pragma unroll
        for (int n = 0; n < 8; n++) {
            #pragma unroll
            for (int m = 0; m < 2; m++) {
                S[m][n][0] = hex2u(S[m][n][0]);
                S[m][n][1] = hex2u(S[m][n][1]);
                rsum2[m][0] = hadd2u(rsum2[m][0], S[m][n][0]);
                rsum2[m][1] = hadd2u(rsum2[m][1], S[m][n][1]);
            }
        }

        {
            const int vrow = (lane & 7) + ((lane >> 3) & 1) * 8;
            const int vcol = ((lane >> 4) & 1) * 8;
            #pragma unroll
            for (int k2 = 0; k2 < 4; k2++) {
                #pragma unroll
                for (int dp = 0; dp < 2; dp++) {
                    uint32_t vf[4];
                    uint32_t a = smem_u32(&Vs[s][(k2 * 16 + vrow) * QPAD + dp * 16 + vcol]);
                    ldmx4t(vf[0], vf[1], vf[2], vf[3], a);
                    #pragma unroll
                    for (int m = 0; m < 2; m++) {
                        mma16816h(o[m][2 * dp],     &S[m][2 * k2][0], vf[0], vf[1]);
                        mma16816h(o[m][2 * dp + 1], &S[m][2 * k2][0], vf[2], vf[3]);
                    }
                }
            }
        }
    }

    #pragma unroll
    for (int m = 0; m < 2; m++)
        #pragma unroll
        for (int rr = 0; rr < 2; rr++) {
            float2 f = h2f2(rsum2[m][rr]);
            float sv = f.x + f.y;
            sv += __shfl_xor_sync(0xFFFFFFFF, sv, 1);
            sv += __shfl_xor_sync(0xFFFFFFFF, sv, 2);
            if ((lane & 3) == 0) {
                const int grow = rowBase + warp * 32 + m * 16 + (lane >> 2) + rr * 8;
                g_rsP[(size_t)z * (BB * NH * HWP) + (size_t)(b * NH + h) * HWP + grow] = sv;
            }
        }

    #pragma unroll
    for (int m = 0; m < 2; m++)
        #pragma unroll
        for (int rr = 0; rr < 2; rr++) {
            const int grow = rowBase + warp * 32 + m * 16 + (lane >> 2) + rr * 8;
            __half* od = g_Oph + (size_t)z * (BB * HWP * DM) + (size_t)(b * HWP + grow) * DM + h * DK;
            #pragma unroll
            for (int n = 0; n < 4; n++)
                *(uint32_t*)(od + n * 8 + c2) = o[m][n][rr];
        }
}

// ---------------------------------------------------------------------------
// Kernel 3: HMMA output projection + residual, fused 3-way KV-split combine.
// ---------------------------------------------------------------------------
__global__ __launch_bounds__(256) void outproj_mma_kernel(
    const float* __restrict__ x, const float* __restrict__ bo,
    const float* __restrict__ gamma_p, float* __restrict__ out)
{
    __shared__ __align__(16) __half ws2[2][64 * QPAD];
    __shared__ __align__(16) __half os2[2][64 * QPAD];

    const int tid  = threadIdx.x;
    const int warp = tid >> 5;
    const int lane = tid & 31;

    const int gp    = blockIdx.x * 64;
    const int b     = gp / HWP;
    const int pb    = gp - b * HWP;
    const int cBase = blockIdx.y * 64;
    const float gamma = *gamma_p;

    const uint32_t wsA = smem_u32(ws2);

    auto load_w = [&](int s, int k0) {
        const char* wb = (const char*)g_Woh + ((size_t)cBase * DM + k0) * 2;
        const int r = tid >> 2, q = tid & 3;
        CPA16(wsA + s * 5120 + r * 80 + q * 16, wb + (size_t)r * (DM * 2) + q * 16);
        CPA_COMMIT();
    };

    const int orow = tid >> 2;
    const int oq   = tid & 3;
    auto load_o = [&](int k0, uint4& a0, uint4& a1, uint4& a2, float& inv) {
        const int hh = k0 >> 5;
        const size_t base = (size_t)(b * HWP + pb + orow) * DM + k0 + oq * 8;
        a0 = *(const uint4*)(g_Oph + base);
        a1 = *(const uint4*)(g_Oph + (size_t)(BB * HWP * DM) + base);
        a2 = *(const uint4*)(g_Oph + (size_t)(2 * BB * HWP * DM) + base);
        const size_t rsi = (size_t)(b * NH + hh) * HWP + pb + orow;
        inv = __fdividef(1.0f, g_rsP[rsi] + g_rsP[(size_t)(BB * NH * HWP) + rsi]
                               + g_rsP[(size_t)(2 * BB * NH * HWP) + rsi]);
    };
    auto store_o = [&](int s, uint4 a0, uint4 a1, uint4 a2, float inv) {
        const uint32_t iv = f2h2(inv, inv);
        uint4 r;
        r.x = hmul2u(hadd2u(hadd2u(a0.x, a1.x), a2.x), iv);
        r.y = hmul2u(hadd2u(hadd2u(a0.y, a1.y), a2.y), iv);
        r.z = hmul2u(hadd2u(hadd2u(a0.z, a1.z), a2.z), iv);
        r.w = hmul2u(hadd2u(hadd2u(a0.w, a1.w), a2.w), iv);
        *(uint4*)(&os2[s][orow * QPAD + oq * 8]) = r;
    };

    const int cw = warp >> 2;
    const int pw = warp & 3;

    float acc[2][2][4] = {};

    load_w(0, 0);
    uint4 oa0, oa1, oa2;
    float oinv;
    load_o(0, oa0, oa1, oa2, oinv);

    for (int c = 0; c < 8; c++) {
        CPA_WAIT0();
        __syncthreads();
        const int s = c & 1;
        store_o(s, oa0, oa1, oa2, oinv);
        if (c < 7) {
            load_w((c + 1) & 1, (c + 1) * 32);
            load_o((c + 1) * 32, oa0, oa1, oa2, oinv);
        }
        __syncthreads();

        const int arow = (lane & 7) + ((lane >> 3) & 1) * 8;
        const int acol = (lane >> 4) * 8;
        const int brow = (lane & 7) + ((lane >> 4) & 1) * 8;
        const int bcol = ((lane >> 3) & 1) * 8;

        #pragma unroll
        for (int ks = 0; ks < 2; ks++) {
            uint32_t af[2][4];
            #pragma unroll
            for (int mt = 0; mt < 2; mt++) {
                uint32_t a = smem_u32(&ws2[s][(cw * 32 + mt * 16 + arow) * QPAD + ks * 16 + acol]);
                ldmx4(af[mt][0], af[mt][1], af[mt][2], af[mt][3], a);
            }
            uint32_t bf[4];
            uint32_t a = smem_u32(&os2[s][(pw * 16 + brow) * QPAD + ks * 16 + bcol]);
            ldmx4(bf[0], bf[1], bf[2], bf[3], a);
            #pragma unroll
            for (int mt = 0; mt < 2; mt++) {
                mma16816f(acc[mt][0], af[mt], bf);
                mma16816f(acc[mt][1], af[mt], bf + 2);
            }
        }
    }

    const int c2 = 2 * (lane & 3);
    #pragma unroll
    for (int mt = 0; mt < 2; mt++) {
        #pragma unroll
        for (int rr = 0; rr < 2; rr++) {
            const int c = cBase + cw * 32 + mt * 16 + (lane >> 2) + rr * 8;
            const float bias = bo[c];
            #pragma unroll
            for (int nt = 0; nt < 2; nt++) {
                const int p = pb + pw * 16 + nt * 8 + c2;
                const size_t idx = (size_t)b * CC * HWP + (size_t)c * HWP + p;
                float2 xv = *(const float2*)(x + idx);
                float2 r;
                r.x = xv.x + gamma * acc[mt][nt][rr * 2 + 0] + bias;
                r.y = xv.y + gamma * acc[mt][nt][rr * 2 + 1] + bias;
                *(float2*)(out + idx) = r;
            }
        }
    }
}

// ---------------------------------------------------------------------------
extern "C" void kernel_launch(void* const* d_in, const int* in_sizes, int n_in,
                              void* d_out, int out_size)
{
    (void)in_sizes; (void)n_in; (void)out_size;
    const float* x   = (const float*)d_in[0];
    const float* Wq  = (const float*)d_in[1];
    const float* bq  = (const float*)d_in[2];
    const float* Wk  = (const float*)d_in[3];
    const float* bk  = (const float*)d_in[4];
    const float* Wv  = (const float*)d_in[5];
    const float* bv  = (const float*)d_in[6];
    const float* Wo  = (const float*)d_in[7];
    const float* bo  = (const float*)d_in[8];
    const float* lam = (const float*)d_in[9];
    const float* gam = (const float*)d_in[10];
    float* out = (float*)d_out;

    prep_kernel<<<548, 256>>>(lam, Wq, Wk, Wv, Wo);
    bias_fill_kernel<<<(HWP * HWP / 2) / 256, 256>>>();
    xt_kernel<<<dim3(HWP / 64, CC / 64, BB), 256>>>(x);

    qkv_mma_kernel<<<dim3(BB * HWP / 64, DM / 64), 256>>>(bq, bk, bv);

    attn_mma_kernel<<<dim3(HWP / 128, BB * NH, NSPLIT), 128>>>();

    outproj_mma_kernel<<<dim3(BB * HWP / 64, CC / 64), 256>>>(x, bo, gam, out);
}

// round 16
// speedup vs baseline: 1.0315x; 1.0315x over previous
#include <cuda_runtime.h>
#include <cuda_fp16.h>
#include <cstdint>

#define BB 2
#define CC 256
#define HH 48
#define WW 48
#define HWP 2304
#define DM 256
#define NH 8
#define DK 32
#define QK_SCALE 0.17677669529663689f   // 1/sqrt(32)
#define LOG2E 1.4426950408889634f
#define QSC (QK_SCALE * LOG2E)           // folded into Q at projection time
#define EXP_OFF 7.0f                     // folded into bias table; cancels in softmax
#define QPAD 40                          // f16 pitch = 80B (16B multiple)
#define WPAD 40
#define NSPLIT 2
#define NTILE (HWP / 64)                 // 36
#define TPS (NTILE / NSPLIT)             // 18 tiles per split

// ---------------- scratch (allocation-free) ----------------
__device__ __half g_Qh[BB * HWP * DM];
__device__ __half g_Kh[BB * HWP * DM];
__device__ __half g_Vh[BB * HWP * DM];
__device__ __half g_Oph[NSPLIT * BB * HWP * DM];   // partial attention out
__device__ float  g_rsP[NSPLIT * BB * NH * HWP];   // partial row sums
__device__ __half g_xh[BB * HWP * CC];             // x transposed (b,p,c)
__device__ __half g_Wqh[DM * CC];
__device__ __half g_Wkh[DM * CC];
__device__ __half g_Wvh[DM * CC];
__device__ __half g_Woh[CC * DM];
__device__ __half g_dtabH[95 * 95];                // f16: lam*exp(-d)*log2e - 7
__device__ __half g_biasH[HWP * HWP];              // fragment-ordered bias (f16)
__device__ __half g_peh[4 * 48 * 64];              // pe table per dBase-tile

// ---------------- helpers ----------------
__device__ __forceinline__ uint32_t smem_u32(const void* p) {
    uint32_t a;
    asm("{ .reg .u64 t; cvta.to.shared.u64 t, %1; cvt.u32.u64 %0, t; }" : "=r"(a) : "l"(p));
    return a;
}
__device__ __forceinline__ void ldmx4(uint32_t& r0, uint32_t& r1, uint32_t& r2, uint32_t& r3, uint32_t a) {
    asm volatile("ldmatrix.sync.aligned.m8n8.x4.shared.b16 {%0,%1,%2,%3}, [%4];"
                 : "=r"(r0), "=r"(r1), "=r"(r2), "=r"(r3) : "r"(a));
}
__device__ __forceinline__ void ldmx4t(uint32_t& r0, uint32_t& r1, uint32_t& r2, uint32_t& r3, uint32_t a) {
    asm volatile("ldmatrix.sync.aligned.m8n8.x4.trans.shared.b16 {%0,%1,%2,%3}, [%4];"
                 : "=r"(r0), "=r"(r1), "=r"(r2), "=r"(r3) : "r"(a));
}
__device__ __forceinline__ void mma16816f(float* c, const uint32_t* a, const uint32_t* b) {
    asm volatile("mma.sync.aligned.m16n8k16.row.col.f32.f16.f16.f32 "
                 "{%0,%1,%2,%3},{%4,%5,%6,%7},{%8,%9},{%0,%1,%2,%3};"
                 : "+f"(c[0]), "+f"(c[1]), "+f"(c[2]), "+f"(c[3])
                 : "r"(a[0]), "r"(a[1]), "r"(a[2]), "r"(a[3]), "r"(b[0]), "r"(b[1]));
}
__device__ __forceinline__ void mma16816h(uint32_t* d, const uint32_t* a, uint32_t b0, uint32_t b1) {
    asm volatile("mma.sync.aligned.m16n8k16.row.col.f16.f16.f16.f16 "
                 "{%0,%1},{%2,%3,%4,%5},{%6,%7},{%0,%1};"
                 : "+r"(d[0]), "+r"(d[1])
                 : "r"(a[0]), "r"(a[1]), "r"(a[2]), "r"(a[3]), "r"(b0), "r"(b1));
}
__device__ __forceinline__ uint32_t f2h2(float lo, float hi) {
    __half2 h = __floats2half2_rn(lo, hi);
    return *(uint32_t*)&h;
}
__device__ __forceinline__ uint32_t hadd2u(uint32_t a, uint32_t b) {
    uint32_t d;
    asm("add.rn.f16x2 %0, %1, %2;" : "=r"(d) : "r"(a), "r"(b));
    return d;
}
__device__ __forceinline__ uint32_t hmul2u(uint32_t a, uint32_t b) {
    uint32_t d;
    asm("mul.rn.f16x2 %0, %1, %2;" : "=r"(d) : "r"(a), "r"(b));
    return d;
}
__device__ __forceinline__ uint32_t hex2u(uint32_t a) {
    uint32_t d;
    asm("ex2.approx.f16x2 %0, %1;" : "=r"(d) : "r"(a));
    return d;
}
__device__ __forceinline__ float2 h2f2(uint32_t u) {
    __half2 h = *(__half2*)&u;
    return __half22float2(h);
}
#define CPA16(dst, src) asm volatile("cp.async.cg.shared.global [%0], [%1], 16;" :: "r"(dst), "l"(src))
#define CPA_COMMIT()    asm volatile("cp.async.commit_group;")
#define CPA_WAIT0()     asm volatile("cp.async.wait_group 0;")

// ---------------------------------------------------------------------------
// Prep A: blocks [0,512): W->f16; [512,548): dtab; [548,596): pe table.
// ---------------------------------------------------------------------------
__global__ __launch_bounds__(256) void prep_kernel(
    const float* __restrict__ lam_p,
    const float* __restrict__ Wq, const float* __restrict__ Wk,
    const float* __restrict__ Wv, const float* __restrict__ Wo)
{
    const int bx = blockIdx.x;
    if (bx < 512) {
        const int idx = bx * 256 + threadIdx.x;
        const int mat = idx >> 15;
        const int off = idx & 32767;
        const float* s = (mat == 0) ? Wq : ((mat == 1) ? Wk : ((mat == 2) ? Wv : Wo));
        uint32_t* d = (uint32_t*)((mat == 0) ? g_Wqh : ((mat == 1) ? g_Wkh : ((mat == 2) ? g_Wvh : g_Woh)));
        d[off] = f2h2(s[off * 2], s[off * 2 + 1]);
    } else if (bx < 548) {
        const int idx = (bx - 512) * 256 + threadIdx.x;
        if (idx >= 95 * 95) return;
        const float lam2 = (*lam_p) * LOG2E;
        const int dy = idx / 95 - 47;
        const int dx = idx % 95 - 47;
        const float t = lam2 * __expf(-sqrtf((float)(dy * dy + dx * dx))) - EXP_OFF;
        g_dtabH[idx] = __float2half(t);
    } else {
        const int idx = (bx - 548) * 256 + threadIdx.x;   // 12288 entries
        const int dt   = idx / 3072;
        const int rem  = idx - dt * 3072;
        const int coord = rem >> 6;
        const int dloc  = rem & 63;
        const int d  = dt * 64 + dloc;
        const int dl = (d < 128) ? d : (d - 128);
        const float freq = __expf(-(float)(dl >> 1) * 0.14391156642875743f);
        const float arg  = (float)coord * freq;
        g_peh[idx] = __float2half((dl & 1) ? __cosf(arg) : __sinf(arg));
    }
}

// ---------------------------------------------------------------------------
// Prep B: expand bias matrix in MMA-fragment order.
// ---------------------------------------------------------------------------
__global__ __launch_bounds__(256) void bias_fill_kernel()
{
    const int idx = blockIdx.x * 256 + threadIdx.x;   // HWP*HWP/2 u32s
    const int blk  = idx >> 11;
    const int rem  = idx & 2047;
    const int w    = rem >> 9;
    const int rem2 = rem & 511;
    const int mn   = rem2 >> 6;
    const int rr   = (rem2 >> 5) & 1;
    const int lane = rem2 & 31;
    const int m = mn >> 3, n = mn & 7;
    const int R = blk / 36, T = blk - R * 36;
    const int i = R * 128 + w * 32 + m * 16 + (lane >> 2) + rr * 8;
    const int j = T * 64 + n * 8 + 2 * (lane & 3);
    const int yi = i / WW, xi = i - yi * WW;
    const int yj0 = j / WW,      xj0 = j - yj0 * WW;
    const int yj1 = (j + 1) / WW, xj1 = (j + 1) - yj1 * WW;
    const unsigned short h0 = *(const unsigned short*)&g_dtabH[(yi - yj0 + 47) * 95 + (xi - xj0 + 47)];
    const unsigned short h1 = *(const unsigned short*)&g_dtabH[(yi - yj1 + 47) * 95 + (xi - xj1 + 47)];
    ((uint32_t*)g_biasH)[idx] = (uint32_t)h0 | ((uint32_t)h1 << 16);
}

// ---------------------------------------------------------------------------
// Prep C: transpose+convert x (b,c,p) fp32 -> g_xh (b,p,c) f16 (vectorized).
// ---------------------------------------------------------------------------
__global__ __launch_bounds__(256) void xt_kernel(const float* __restrict__ x)
{
    __shared__ float ts[64][65];
    const int b  = blockIdx.z;
    const int pB = blockIdx.x * 64;
    const int cB = blockIdx.y * 64;
    #pragma unroll
    for (int i = threadIdx.x; i < 1024; i += 256) {
        const int c  = i >> 4;
        const int pq = (i & 15) * 4;
        const float4 v = *(const float4*)&x[((size_t)b * CC + cB + c) * HWP + pB + pq];
        ts[c][pq + 0] = v.x;
        ts[c][pq + 1] = v.y;
        ts[c][pq + 2] = v.z;
        ts[c][pq + 3] = v.w;
    }
    __syncthreads();
    #pragma unroll
    for (int i = threadIdx.x; i < 1024; i += 256) {
        const int p  = i >> 4;
        const int cq = (i & 15) * 4;
        uint2 o;
        o.x = f2h2(ts[cq + 0][p], ts[cq + 1][p]);
        o.y = f2h2(ts[cq + 2][p], ts[cq + 3][p]);
        *(uint2*)(g_xh + ((size_t)(b * HWP + pB + p) * CC + cB + cq)) = o;
    }
}

// ---------------------------------------------------------------------------
// Kernel 1: HMMA fused QKV + pe + bias; f16 accumulate; pe table from gmem.
// ---------------------------------------------------------------------------
__global__ __launch_bounds__(256) void qkv_mma_kernel(
    const float* __restrict__ bq, const float* __restrict__ bk, const float* __restrict__ bv)
{
    __shared__ __align__(16) __half As[2][64 * QPAD];
    __shared__ __align__(16) __half Ws[2][3][64 * WPAD];
    __shared__ __align__(16) __half pes[48 * 64];

    const int tid  = threadIdx.x;
    const int warp = tid >> 5;
    const int lane = tid & 31;

    const int gp    = blockIdx.x * 64;
    const int b     = gp / HWP;
    const int pb    = gp - b * HWP;
    const int dBase = blockIdx.y * 64;
    const bool use_y = (dBase >= 128);

    const uint32_t asA = smem_u32(As);
    const uint32_t wsA = smem_u32(Ws);

    const __half* gW[3] = { g_Wqh, g_Wkh, g_Wvh };

    auto load_chunk = [&](int s, int c0) {
        const char* ab = (const char*)g_xh + ((size_t)(b * HWP + pb) * CC + c0) * 2;
        {
            const int i = tid;
            const int r = i >> 2, q = i & 3;
            CPA16(asA + s * 5120 + r * 80 + q * 16, ab + (size_t)r * (CC * 2) + q * 16);
        }
        #pragma unroll
        for (int i = tid; i < 768; i += 256) {
            const int mat = i / 256;
            const int rem = i - mat * 256;
            const int r = rem >> 2, q = rem & 3;
            const char* wb = (const char*)gW[mat] + ((size_t)(dBase + r) * CC + c0) * 2;
            CPA16(wsA + s * 15360 + mat * 5120 + r * 80 + q * 16, wb + q * 16);
        }
        CPA_COMMIT();
    };

    const int mw = warp >> 2;
    const int nw = warp & 3;

    uint32_t acc[3][2][2][2] = {};    // f16x2 accumulators [mat][mt][nt][rr]

    load_chunk(0, 0);

    // pe table load (covered by first pipeline wait)
    {
        const uint32_t* src = (const uint32_t*)g_peh + (dBase >> 6) * 1536;
        #pragma unroll
        for (int i = tid; i < 1536; i += 256)
            ((uint32_t*)pes)[i] = src[i];
    }

    for (int c = 0; c < 8; c++) {
        CPA_WAIT0();
        __syncthreads();
        if (c < 7) load_chunk((c + 1) & 1, (c + 1) * 32);

        const int s = c & 1;
        const __half* Ab = As[s];

        const int arow = (lane & 7) + ((lane >> 3) & 1) * 8;
        const int acol = (lane >> 4) * 8;
        const int brow = (lane & 7) + ((lane >> 4) & 1) * 8;
        const int bcol = ((lane >> 3) & 1) * 8;

        #pragma unroll
        for (int ks = 0; ks < 2; ks++) {
            uint32_t af[2][4];
            #pragma unroll
            for (int mt = 0; mt < 2; mt++) {
                uint32_t a = smem_u32(Ab + (mw * 32 + mt * 16 + arow) * QPAD + ks * 16 + acol);
                ldmx4(af[mt][0], af[mt][1], af[mt][2], af[mt][3], a);
            }
            #pragma unroll
            for (int mat = 0; mat < 3; mat++) {
                uint32_t bf[4];
                uint32_t a = smem_u32(&Ws[s][mat][(nw * 16 + brow) * WPAD + ks * 16 + bcol]);
                ldmx4(bf[0], bf[1], bf[2], bf[3], a);
                #pragma unroll
                for (int mt = 0; mt < 2; mt++) {
                    mma16816h(acc[mat][mt][0], af[mt], bf[0], bf[1]);
                    mma16816h(acc[mat][mt][1], af[mt], bf[2], bf[3]);
                }
            }
        }
    }

    const int c2 = 2 * (lane & 3);
    #pragma unroll
    for (int mt = 0; mt < 2; mt++) {
        #pragma unroll
        for (int rr = 0; rr < 2; rr++) {
            const int ploc = mw * 32 + mt * 16 + (lane >> 2) + rr * 8;
            const int p    = pb + ploc;
            const int coord = use_y ? (p / WW) : (p % WW);
            const size_t rowIdx = ((size_t)b * HWP + p) * DM + dBase;
            #pragma unroll
            for (int nt = 0; nt < 2; nt++) {
                const int dloc = nw * 16 + nt * 8 + c2;
                const int d    = dBase + dloc;
                const float pe0 = __half2float(pes[coord * 64 + dloc]);
                const float pe1 = __half2float(pes[coord * 64 + dloc + 1]);
                const float2 fq = h2f2(acc[0][mt][nt][rr]);
                const float2 fk = h2f2(acc[1][mt][nt][rr]);
                const float2 fv = h2f2(acc[2][mt][nt][rr]);
                const float q0 = (fq.x + bq[d]     + pe0) * QSC;
                const float q1 = (fq.y + bq[d + 1] + pe1) * QSC;
                const float k0 = fk.x + bk[d]     + pe0;
                const float k1 = fk.y + bk[d + 1] + pe1;
                const float v0 = fv.x + bv[d];
                const float v1 = fv.y + bv[d + 1];
                *(uint32_t*)(g_Qh + rowIdx + dloc) = f2h2(q0, q1);
                *(uint32_t*)(g_Kh + rowIdx + dloc) = f2h2(k0, k1);
                *(uint32_t*)(g_Vh + rowIdx + dloc) = f2h2(v0, v1);
            }
        }
    }
}

// ---------------------------------------------------------------------------
// Kernel 2: f16 HMMA flash attention, KV-split, bias as MMA C-init (R14 form).
// ---------------------------------------------------------------------------
__global__ __launch_bounds__(128, 4) void attn_mma_kernel()
{
    __shared__ __align__(16) __half Qs[128 * QPAD];
    __shared__ __align__(16) __half Ks[2][64 * QPAD];
    __shared__ __align__(16) __half Vs[2][64 * QPAD];

    const int tid  = threadIdx.x;
    const int warp = tid >> 5;
    const int lane = tid & 31;
    const int b    = blockIdx.y >> 3;
    const int h    = blockIdx.y & 7;
    const int rowBase = blockIdx.x * 128;
    const int z    = blockIdx.z;
    const int tBeg = z * TPS;

    const uint32_t ksA = smem_u32(Ks);
    const uint32_t vsA = smem_u32(Vs);

    auto issue_tile = [&](int t, int s) {
        const int jt = t * 64;
        const char* kb = (const char*)g_Kh + ((size_t)(b * HWP + jt) * DM + h * DK) * 2;
        const char* vb = (const char*)g_Vh + ((size_t)(b * HWP + jt) * DM + h * DK) * 2;
        #pragma unroll
        for (int i = tid; i < 256; i += 128) {
            const int r = i >> 2, q = i & 3;
            CPA16(ksA + s * 5120 + r * 80 + q * 16, kb + (size_t)r * (DM * 2) + q * 16);
            CPA16(vsA + s * 5120 + r * 80 + q * 16, vb + (size_t)r * (DM * 2) + q * 16);
        }
        CPA_COMMIT();
    };

    {
        const __half* qsrc = g_Qh + (size_t)(b * HWP + rowBase) * DM + h * DK;
        #pragma unroll
        for (int i = tid; i < 512; i += 128) {
            const int r = i >> 2, q = i & 3;
            *(uint4*)(Qs + r * QPAD + q * 8) = *(const uint4*)(qsrc + (size_t)r * DM + q * 8);
        }
    }
    issue_tile(tBeg, 0);
    __syncthreads();

    uint32_t qa[2][2][4];
    {
        const int arow = (lane & 7) + ((lane >> 3) & 1) * 8;
        const int acol = (lane >> 4) * 8;
        #pragma unroll
        for (int m = 0; m < 2; m++)
            #pragma unroll
            for (int ks = 0; ks < 2; ks++) {
                uint32_t a = smem_u32(Qs + (warp * 32 + m * 16 + arow) * QPAD + ks * 16 + acol);
                ldmx4(qa[m][ks][0], qa[m][ks][1], qa[m][ks][2], qa[m][ks][3], a);
            }
    }

    const int c2 = 2 * (lane & 3);
    const uint32_t* bbase = (const uint32_t*)g_biasH
        + (size_t)blockIdx.x * 36 * 2048 + warp * 512 + lane;

    uint32_t o[2][4][2];
    uint32_t rsum2[2][2];
    #pragma unroll
    for (int m = 0; m < 2; m++) {
        #pragma unroll
        for (int n = 0; n < 4; n++) { o[m][n][0] = 0u; o[m][n][1] = 0u; }
        rsum2[m][0] = 0u; rsum2[m][1] = 0u;
    }

    for (int t = 0; t < TPS; t++) {
        uint32_t S[2][8][2];
        {
            const uint32_t* bt = bbase + (size_t)(tBeg + t) * 2048;
            #pragma unroll
            for (int m = 0; m < 2; m++)
                #pragma unroll
                for (int n = 0; n < 8; n++) {
                    S[m][n][0] = __ldg(bt + (m * 8 + n) * 64);
                    S[m][n][1] = __ldg(bt + (m * 8 + n) * 64 + 32);
                }
        }

        CPA_WAIT0();
        __syncthreads();
        if (t < TPS - 1) issue_tile(tBeg + t + 1, (t + 1) & 1);
        const int s = t & 1;

        {
            const int brow = (lane & 7) + ((lane >> 4) & 1) * 8;
            const int bcol = ((lane >> 3) & 1) * 8;
            #pragma unroll
            for (int np = 0; np < 4; np++) {
                #pragma unroll
                for (int ks = 0; ks < 2; ks++) {
                    uint32_t kf[4];
                    uint32_t a = smem_u32(&Ks[s][(np * 16 + brow) * QPAD + ks * 16 + bcol]);
                    ldmx4(kf[0], kf[1], kf[2], kf[3], a);
                    #pragma unroll
                    for (int m = 0; m < 2; m++) {
                        mma16816h(S[m][2 * np],     qa[m][ks], kf[0], kf[1]);
                        mma16816h(S[m][2 * np + 1], qa[m][ks], kf[2], kf[3]);
                    }
                }
            }
        }

        #pragma unroll
        for (int n = 0; n < 8; n++) {
            #pragma unroll
            for (int m = 0; m < 2; m++) {
                S[m][n][0] = hex2u(S[m][n][0]);
                S[m][n][1] = hex2u(S[m][n][1]);
                rsum2[m][0] = hadd2u(rsum2[m][0], S[m][n][0]);
                rsum2[m][1] = hadd2u(rsum2[m][1], S[m][n][1]);
            }
        }

        {
            const int vrow = (lane & 7) + ((lane >> 3) & 1) * 8;
            const int vcol = ((lane >> 4) & 1) * 8;
            #pragma unroll
            for (int k2 = 0; k2 < 4; k2++) {
                #pragma unroll
                for (int dp = 0; dp < 2; dp++) {
                    uint32_t vf[4];
                    uint32_t a = smem_u32(&Vs[s][(k2 * 16 + vrow) * QPAD + dp * 16 + vcol]);
                    ldmx4t(vf[0], vf[1], vf[2], vf[3], a);
                    #pragma unroll
                    for (int m = 0; m < 2; m++) {
                        mma16816h(o[m][2 * dp],     &S[m][2 * k2][0], vf[0], vf[1]);
                        mma16816h(o[m][2 * dp + 1], &S[m][2 * k2][0], vf[2], vf[3]);
                    }
                }
            }
        }
    }

    #pragma unroll
    for (int m = 0; m < 2; m++)
        #pragma unroll
        for (int rr = 0; rr < 2; rr++) {
            float2 f = h2f2(rsum2[m][rr]);
            float sv = f.x + f.y;
            sv += __shfl_xor_sync(0xFFFFFFFF, sv, 1);
            sv += __shfl_xor_sync(0xFFFFFFFF, sv, 2);
            if ((lane & 3) == 0) {
                const int grow = rowBase + warp * 32 + m * 16 + (lane >> 2) + rr * 8;
                g_rsP[(size_t)z * (BB * NH * HWP) + (size_t)(b * NH + h) * HWP + grow] = sv;
            }
        }

    #pragma unroll
    for (int m = 0; m < 2; m++)
        #pragma unroll
        for (int rr = 0; rr < 2; rr++) {
            const int grow = rowBase + warp * 32 + m * 16 + (lane >> 2) + rr * 8;
            __half* od = g_Oph + (size_t)z * (BB * HWP * DM) + (size_t)(b * HWP + grow) * DM + h * DK;
            #pragma unroll
            for (int n = 0; n < 4; n++)
                *(uint32_t*)(od + n * 8 + c2) = o[m][n][rr];
        }
}

// ---------------------------------------------------------------------------
// Kernel 3: HMMA output projection + residual, fused 2-way KV-split combine.
// ---------------------------------------------------------------------------
__global__ __launch_bounds__(256) void outproj_mma_kernel(
    const float* __restrict__ x, const float* __restrict__ bo,
    const float* __restrict__ gamma_p, float* __restrict__ out)
{
    __shared__ __align__(16) __half ws2[2][64 * QPAD];
    __shared__ __align__(16) __half os2[2][64 * QPAD];

    const int tid  = threadIdx.x;
    const int warp = tid >> 5;
    const int lane = tid & 31;

    const int gp    = blockIdx.x * 64;
    const int b     = gp / HWP;
    const int pb    = gp - b * HWP;
    const int cBase = blockIdx.y * 64;
    const float gamma = *gamma_p;

    const uint32_t wsA = smem_u32(ws2);

    auto load_w = [&](int s, int k0) {
        const char* wb = (const char*)g_Woh + ((size_t)cBase * DM + k0) * 2;
        const int r = tid >> 2, q = tid & 3;
        CPA16(wsA + s * 5120 + r * 80 + q * 16, wb + (size_t)r * (DM * 2) + q * 16);
        CPA_COMMIT();
    };

    const int orow = tid >> 2;
    const int oq   = tid & 3;
    auto load_o = [&](int k0, uint4& a0, uint4& a1, float& inv) {
        const int hh = k0 >> 5;
        const size_t base = (size_t)(b * HWP + pb + orow) * DM + k0 + oq * 8;
        a0 = *(const uint4*)(g_Oph + base);
        a1 = *(const uint4*)(g_Oph + (size_t)(BB * HWP * DM) + base);
        const size_t rsi = (size_t)(b * NH + hh) * HWP + pb + orow;
        inv = __fdividef(1.0f, g_rsP[rsi] + g_rsP[(size_t)(BB * NH * HWP) + rsi]);
    };
    auto store_o = [&](int s, uint4 a0, uint4 a1, float inv) {
        const uint32_t iv = f2h2(inv, inv);
        uint4 r;
        r.x = hmul2u(hadd2u(a0.x, a1.x), iv);
        r.y = hmul2u(hadd2u(a0.y, a1.y), iv);
        r.z = hmul2u(hadd2u(a0.z, a1.z), iv);
        r.w = hmul2u(hadd2u(a0.w, a1.w), iv);
        *(uint4*)(&os2[s][orow * QPAD + oq * 8]) = r;
    };

    const int cw = warp >> 2;
    const int pw = warp & 3;

    float acc[2][2][4] = {};

    load_w(0, 0);
    uint4 oa0, oa1;
    float oinv;
    load_o(0, oa0, oa1, oinv);

    for (int c = 0; c < 8; c++) {
        CPA_WAIT0();
        __syncthreads();
        const int s = c & 1;
        store_o(s, oa0, oa1, oinv);
        if (c < 7) {
            load_w((c + 1) & 1, (c + 1) * 32);
            load_o((c + 1) * 32, oa0, oa1, oinv);
        }
        __syncthreads();

        const int arow = (lane & 7) + ((lane >> 3) & 1) * 8;
        const int acol = (lane >> 4) * 8;
        const int brow = (lane & 7) + ((lane >> 4) & 1) * 8;
        const int bcol = ((lane >> 3) & 1) * 8;

        #pragma unroll
        for (int ks = 0; ks < 2; ks++) {
            uint32_t af[2][4];
            #pragma unroll
            for (int mt = 0; mt < 2; mt++) {
                uint32_t a = smem_u32(&ws2[s][(cw * 32 + mt * 16 + arow) * QPAD + ks * 16 + acol]);
                ldmx4(af[mt][0], af[mt][1], af[mt][2], af[mt][3], a);
            }
            uint32_t bf[4];
            uint32_t a = smem_u32(&os2[s][(pw * 16 + brow) * QPAD + ks * 16 + bcol]);
            ldmx4(bf[0], bf[1], bf[2], bf[3], a);
            #pragma unroll
            for (int mt = 0; mt < 2; mt++) {
                mma16816f(acc[mt][0], af[mt], bf);
                mma16816f(acc[mt][1], af[mt], bf + 2);
            }
        }
    }

    const int c2 = 2 * (lane & 3);
    #pragma unroll
    for (int mt = 0; mt < 2; mt++) {
        #pragma unroll
        for (int rr = 0; rr < 2; rr++) {
            const int c = cBase + cw * 32 + mt * 16 + (lane >> 2) + rr * 8;
            const float bias = bo[c];
            #pragma unroll
            for (int nt = 0; nt < 2; nt++) {
                const int p = pb + pw * 16 + nt * 8 + c2;
                const size_t idx = (size_t)b * CC * HWP + (size_t)c * HWP + p;
                float2 xv = *(const float2*)(x + idx);
                float2 r;
                r.x = xv.x + gamma * acc[mt][nt][rr * 2 + 0] + bias;
                r.y = xv.y + gamma * acc[mt][nt][rr * 2 + 1] + bias;
                *(float2*)(out + idx) = r;
            }
        }
    }
}

// ---------------------------------------------------------------------------
extern "C" void kernel_launch(void* const* d_in, const int* in_sizes, int n_in,
                              void* d_out, int out_size)
{
    (void)in_sizes; (void)n_in; (void)out_size;
    const float* x   = (const float*)d_in[0];
    const float* Wq  = (const float*)d_in[1];
    const float* bq  = (const float*)d_in[2];
    const float* Wk  = (const float*)d_in[3];
    const float* bk  = (const float*)d_in[4];
    const float* Wv  = (const float*)d_in[5];
    const float* bv  = (const float*)d_in[6];
    const float* Wo  = (const float*)d_in[7];
    const float* bo  = (const float*)d_in[8];
    const float* lam = (const float*)d_in[9];
    const float* gam = (const float*)d_in[10];
    float* out = (float*)d_out;

    prep_kernel<<<596, 256>>>(lam, Wq, Wk, Wv, Wo);
    bias_fill_kernel<<<(HWP * HWP / 2) / 256, 256>>>();
    xt_kernel<<<dim3(HWP / 64, CC / 64, BB), 256>>>(x);

    qkv_mma_kernel<<<dim3(BB * HWP / 64, DM / 64), 256>>>(bq, bk, bv);

    attn_mma_kernel<<<dim3(HWP / 128, BB * NH, NSPLIT), 128>>>();

    outproj_mma_kernel<<<dim3(BB * HWP / 64, CC / 64), 256>>>(x, bo, gam, out);
}